// round 10
// baseline (speedup 1.0000x reference)
#include <cuda_runtime.h>
#include <cuda_bf16.h>

// out = x > 0 ? 0.9*x + 0.1*tanh(x) : 0.5*tanh(x)
// Elementwise over 8192*8192 fp32. Pure HBM-streaming kernel.
//
// FINAL CONVERGED design: 256-bit loads/stores (ld/st.global.v8.f32), 2 x v8
// per thread front-batched, strided for perfect coalescing, MUFU.TANH
// compute, .cs streaming hints, 512-thread CTAs.
//
// Six structurally distinct variants (vec4 x {1,4,8}, v8x2 x {256,512}t,
// persistent pipelined) all pin at 74.6-75.4us kernel / ~6450 GB/s = ~81%
// of HBM spec — the read/write-turnaround floor for a 1:1 streaming mix on
// B300. SM issue is 16% (idle); bytes are irreducible. Converged.

__device__ __forceinline__ float fast_tanh(float x) {
    float y;
    asm("tanh.approx.f32 %0, %1;" : "=f"(y) : "f"(x));
    return y;
}

__device__ __forceinline__ float act(float x) {
    float t = fast_tanh(x);
    return (x > 0.0f) ? fmaf(x, 0.9f, t * 0.1f) : (t * 0.5f);
}

struct V8 { float v[8]; };

__device__ __forceinline__ V8 ldg256_cs(const float* p) {
    V8 r;
    asm("ld.global.cs.v8.f32 {%0,%1,%2,%3,%4,%5,%6,%7}, [%8];"
        : "=f"(r.v[0]), "=f"(r.v[1]), "=f"(r.v[2]), "=f"(r.v[3]),
          "=f"(r.v[4]), "=f"(r.v[5]), "=f"(r.v[6]), "=f"(r.v[7])
        : "l"(p));
    return r;
}

__device__ __forceinline__ void stg256_cs(float* p, const V8& r) {
    asm("st.global.cs.v8.f32 [%0], {%1,%2,%3,%4,%5,%6,%7,%8};"
        :: "l"(p),
           "f"(r.v[0]), "f"(r.v[1]), "f"(r.v[2]), "f"(r.v[3]),
           "f"(r.v[4]), "f"(r.v[5]), "f"(r.v[6]), "f"(r.v[7])
        : "memory");
}

__device__ __forceinline__ V8 act8(V8 a) {
    V8 r;
#pragma unroll
    for (int k = 0; k < 8; k++) r.v[k] = act(a.v[k]);
    return r;
}

// Fast path: n = 16 * total_threads exactly. Each thread: 2 x 256-bit
// load front-batched, strided by 8*total_threads floats for coalescing.
__global__ void __launch_bounds__(512)
activation_v8x2_kernel(const float* __restrict__ in, float* __restrict__ out,
                       long long stride8 /* = 8 * total_threads (floats) */) {
    long long i = (long long)(blockIdx.x * blockDim.x + threadIdx.x) * 8;

    V8 a = ldg256_cs(in + i);
    V8 b = ldg256_cs(in + i + stride8);

    stg256_cs(out + i,           act8(a));
    stg256_cs(out + i + stride8, act8(b));
}

__device__ __forceinline__ float4 act4(float4 v) {
    float4 r;
    r.x = act(v.x); r.y = act(v.y); r.z = act(v.z); r.w = act(v.w);
    return r;
}

// Generic path (bounds-checked grid-stride, 128-bit).
__global__ void __launch_bounds__(256)
activation_vec4_kernel(const float4* __restrict__ in, float4* __restrict__ out, int n4) {
    int i = blockIdx.x * blockDim.x + threadIdx.x;
    int stride = gridDim.x * blockDim.x;
    for (; i < n4; i += stride) {
        __stcs(&out[i], act4(__ldcs(&in[i])));
    }
}

__global__ void __launch_bounds__(256)
activation_tail_kernel(const float* __restrict__ in, float* __restrict__ out,
                       int start, int n) {
    int i = start + blockIdx.x * blockDim.x + threadIdx.x;
    if (i < n) out[i] = act(in[i]);
}

extern "C" void kernel_launch(void* const* d_in, const int* in_sizes, int n_in,
                              void* d_out, int out_size) {
    const float* x = (const float*)d_in[0];
    float* out = (float*)d_out;
    int n = in_sizes[0];

    const int threads = 512;

    // Fast path: 16 floats per thread (2 x v8), exact division.
    if (n > 0 && (n % (16 * threads)) == 0) {
        long long total_threads = n / 16;
        int blocks = (int)(total_threads / threads);
        activation_v8x2_kernel<<<blocks, threads>>>(x, out, 8LL * total_threads);
        return;
    }

    int n4 = n / 4;
    if (n4 > 0) {
        int blocks = (n4 + 255) / 256;
        if (blocks > 65535 * 2) blocks = 65535 * 2;
        activation_vec4_kernel<<<blocks, 256>>>(
            (const float4*)x, (float4*)out, n4);
    }
    int rem = n - n4 * 4;
    if (rem > 0) {
        activation_tail_kernel<<<1, 256>>>(x, out, n4 * 4, n);
    }
}

// round 11
// speedup vs baseline: 1.0066x; 1.0066x over previous
#include <cuda_runtime.h>
#include <cuda_bf16.h>

// out = x > 0 ? 0.9*x + 0.1*tanh(x) : 0.5*tanh(x)
// Elementwise over 8192*8192 fp32. Pure HBM-streaming kernel.
//
// FINAL (best measured: 74.56us kernel / 81.98us wall): 256-bit
// loads/stores (ld/st.global.v8.f32), 2 x v8 per thread front-batched,
// strided for perfect coalescing, MUFU.TANH compute, .cs streaming hints,
// 256-thread CTAs.
//
// Convergence evidence (7 rounds): all byte-preserving variants — vec4 x
// {1,4,8} per thread, v8x2 at 256t and 512t, persistent pipelined — pin at
// 74.6-75.4us kernel / 6410-6470 GB/s = ~81% of HBM spec. That is the
// B300 read/write-turnaround floor for a 1:1 streaming mix. SM issue 16%
// (idle), bytes irreducible (no reuse, fp32->fp32, 512MB >> L2). Done.

__device__ __forceinline__ float fast_tanh(float x) {
    float y;
    asm("tanh.approx.f32 %0, %1;" : "=f"(y) : "f"(x));
    return y;
}

__device__ __forceinline__ float act(float x) {
    float t = fast_tanh(x);
    return (x > 0.0f) ? fmaf(x, 0.9f, t * 0.1f) : (t * 0.5f);
}

struct V8 { float v[8]; };

__device__ __forceinline__ V8 ldg256_cs(const float* p) {
    V8 r;
    asm("ld.global.cs.v8.f32 {%0,%1,%2,%3,%4,%5,%6,%7}, [%8];"
        : "=f"(r.v[0]), "=f"(r.v[1]), "=f"(r.v[2]), "=f"(r.v[3]),
          "=f"(r.v[4]), "=f"(r.v[5]), "=f"(r.v[6]), "=f"(r.v[7])
        : "l"(p));
    return r;
}

__device__ __forceinline__ void stg256_cs(float* p, const V8& r) {
    asm("st.global.cs.v8.f32 [%0], {%1,%2,%3,%4,%5,%6,%7,%8};"
        :: "l"(p),
           "f"(r.v[0]), "f"(r.v[1]), "f"(r.v[2]), "f"(r.v[3]),
           "f"(r.v[4]), "f"(r.v[5]), "f"(r.v[6]), "f"(r.v[7])
        : "memory");
}

__device__ __forceinline__ V8 act8(V8 a) {
    V8 r;
#pragma unroll
    for (int k = 0; k < 8; k++) r.v[k] = act(a.v[k]);
    return r;
}

// Fast path: n = 16 * total_threads exactly. Each thread: 2 x 256-bit
// load front-batched, strided by 8*total_threads floats for coalescing.
__global__ void __launch_bounds__(256)
activation_v8x2_kernel(const float* __restrict__ in, float* __restrict__ out,
                       long long stride8 /* = 8 * total_threads (floats) */) {
    long long i = (long long)(blockIdx.x * blockDim.x + threadIdx.x) * 8;

    V8 a = ldg256_cs(in + i);
    V8 b = ldg256_cs(in + i + stride8);

    stg256_cs(out + i,           act8(a));
    stg256_cs(out + i + stride8, act8(b));
}

__device__ __forceinline__ float4 act4(float4 v) {
    float4 r;
    r.x = act(v.x); r.y = act(v.y); r.z = act(v.z); r.w = act(v.w);
    return r;
}

// Generic path (bounds-checked grid-stride, 128-bit).
__global__ void __launch_bounds__(256)
activation_vec4_kernel(const float4* __restrict__ in, float4* __restrict__ out, int n4) {
    int i = blockIdx.x * blockDim.x + threadIdx.x;
    int stride = gridDim.x * blockDim.x;
    for (; i < n4; i += stride) {
        __stcs(&out[i], act4(__ldcs(&in[i])));
    }
}

__global__ void __launch_bounds__(256)
activation_tail_kernel(const float* __restrict__ in, float* __restrict__ out,
                       int start, int n) {
    int i = start + blockIdx.x * blockDim.x + threadIdx.x;
    if (i < n) out[i] = act(in[i]);
}

extern "C" void kernel_launch(void* const* d_in, const int* in_sizes, int n_in,
                              void* d_out, int out_size) {
    const float* x = (const float*)d_in[0];
    float* out = (float*)d_out;
    int n = in_sizes[0];

    const int threads = 256;

    // Fast path: 16 floats per thread (2 x v8), exact division.
    if (n > 0 && (n % (16 * threads)) == 0) {
        long long total_threads = n / 16;
        int blocks = (int)(total_threads / threads);
        activation_v8x2_kernel<<<blocks, threads>>>(x, out, 8LL * total_threads);
        return;
    }

    int n4 = n / 4;
    if (n4 > 0) {
        int blocks = (n4 + threads - 1) / threads;
        if (blocks > 65535 * 2) blocks = 65535 * 2;
        activation_vec4_kernel<<<blocks, threads>>>(
            (const float4*)x, (float4*)out, n4);
    }
    int rem = n - n4 * 4;
    if (rem > 0) {
        activation_tail_kernel<<<1, 256>>>(x, out, n4 * 4, n);
    }
}